// round 17
// baseline (speedup 1.0000x reference)
#include <cuda_runtime.h>
#include <cuda_fp16.h>
#include <cstdint>

#define NPIX 4096
#define NB 4
#define CIN 256

__device__ unsigned g_qh[(size_t)16 * NPIX * 16];
__device__ unsigned g_kh[(size_t)16 * NPIX * 16];
__device__ unsigned g_vh[(size_t)16 * 32 * (NPIX / 2)];
__device__ unsigned g_wh[384 * 128];
__device__ unsigned g_xh[(size_t)NB * NPIX * 128];
__device__ unsigned g_w2hi[256 * 64], g_w2lo[256 * 64];
__device__ unsigned g_aohi[(size_t)NB * NPIX * 64];
__device__ unsigned g_aolo[(size_t)NB * NPIX * 64];

__device__ __forceinline__ void cpasync16(unsigned dst, const void* src) {
    asm volatile("cp.async.ca.shared.global [%0], [%1], 16;" :: "r"(dst), "l"(src));
}
__device__ __forceinline__ unsigned packh2(float hi, float lo) {
    unsigned r; asm("cvt.rn.f16x2.f32 %0, %1, %2;" : "=r"(r) : "f"(hi), "f"(lo)); return r;
}
__device__ __forceinline__ unsigned h2exp2(unsigned x) {
    unsigned r; asm("ex2.approx.f16x2 %0, %1;" : "=r"(r) : "r"(x)); return r;
}
__device__ __forceinline__ void ldm4(unsigned* r, unsigned a) {
    asm volatile("ldmatrix.sync.aligned.m8n8.x4.shared.b16 {%0,%1,%2,%3}, [%4];"
                 : "=r"(r[0]), "=r"(r[1]), "=r"(r[2]), "=r"(r[3]) : "r"(a));
}
__device__ __forceinline__ void mma_f16(float* d, unsigned a0, unsigned a1,
                                        unsigned a2, unsigned a3, unsigned b0, unsigned b1) {
    asm volatile("mma.sync.aligned.m16n8k16.row.col.f32.f16.f16.f32 "
                 "{%0,%1,%2,%3}, {%4,%5,%6,%7}, {%8,%9}, {%0,%1,%2,%3};"
                 : "+f"(d[0]), "+f"(d[1]), "+f"(d[2]), "+f"(d[3])
                 : "r"(a0), "r"(a1), "r"(a2), "r"(a3), "r"(b0), "r"(b1));
}

// ---------------- converters ----------------
__global__ void cvtw_kernel(const float* __restrict__ w_qkv, unsigned* __restrict__ wh,
                            const float* __restrict__ w_out,
                            unsigned* __restrict__ whi, unsigned* __restrict__ wlo)
{
    int i = blockIdx.x * 256 + threadIdx.x;
    wh[i] = packh2(w_qkv[2 * i + 1], w_qkv[2 * i]);
    if (i < 16384) {
        float a = w_out[2 * i], bb = w_out[2 * i + 1];
        __half ha = __float2half_rn(a), hb = __float2half_rn(bb);
        whi[i] = (unsigned)__half_as_ushort(ha) | ((unsigned)__half_as_ushort(hb) << 16);
        wlo[i] = packh2(bb - __half2float(hb), a - __half2float(ha));
    }
}
__global__ __launch_bounds__(256) void xcvt_kernel(const float* __restrict__ x,
                                                   unsigned* __restrict__ xh)
{
    __shared__ float t[64][65];
    const int pix0 = blockIdx.x * 64, k0 = blockIdx.y * 64, b = blockIdx.z;
    const int tid = threadIdx.x;
#pragma unroll
    for (int j = 0; j < 16; j++) {
        int row = j * 4 + (tid >> 6), col = tid & 63;
        t[row][col] = x[((size_t)b * 256 + k0 + row) * NPIX + pix0 + col];
    }
    __syncthreads();
    int p = tid >> 2, seg = tid & 3;
    unsigned u[8];
#pragma unroll
    for (int j = 0; j < 8; j++)
        u[j] = packh2(t[seg * 16 + 2 * j + 1][p], t[seg * 16 + 2 * j][p]);
    unsigned* dst = xh + ((size_t)b * NPIX + pix0 + p) * 128 + k0 / 2 + seg * 8;
    *(uint4*)dst       = make_uint4(u[0], u[1], u[2], u[3]);
    *(uint4*)(dst + 4) = make_uint4(u[4], u[5], u[6], u[7]);
}

// ---------------------------------------------------------------------------
// fp16 QKV GEMM + fused l2norm: BK=64, 2-stage (unchanged from round 16).
// ---------------------------------------------------------------------------
#define GQ 36
#define QKVSM (4 * 128 * GQ * 4)

__global__ __launch_bounds__(256) void gemm_qkv_h(
    const unsigned* __restrict__ wh, const unsigned* __restrict__ xh,
    unsigned* __restrict__ qh, unsigned* __restrict__ kh, unsigned* __restrict__ vh)
{
    extern __shared__ unsigned gsm[];
    unsigned* sXoff = gsm + 2 * 128 * GQ;

    const int sel = blockIdx.y, b = blockIdx.z;
    const int pixB = blockIdx.x * 128;
    const int tid = threadIdx.x, lane = tid & 31, warp = tid >> 5;
    const int g = lane >> 2, c = lane & 3;
    const int head = warp & 3, nh = warp >> 2;
    const int pix0 = pixB + nh * 64;
    const unsigned wsb = (unsigned)__cvta_generic_to_shared(gsm);
    const unsigned xsb = (unsigned)__cvta_generic_to_shared(sXoff);
    const unsigned aRow = (unsigned)((lane & 15) * GQ + ((lane >> 4) & 1) * 4);
    const unsigned bRow = (unsigned)(((lane & 7) + ((lane >> 4) & 1) * 8) * GQ + ((lane >> 3) & 1) * 4);

    float acc[2][8][4];
#pragma unroll
    for (int mt = 0; mt < 2; mt++)
#pragma unroll
        for (int nt = 0; nt < 8; nt++)
#pragma unroll
            for (int r = 0; r < 4; r++) acc[mt][nt][r] = 0.f;

    auto fill = [&](int kk, int s) {
        int row = tid >> 1, sg = tid & 1;
        const unsigned* ws = wh + (size_t)(sel * 128 + row) * 128 + kk / 2 + sg * 16;
        const unsigned* xs = xh + ((size_t)b * NPIX + pixB + row) * 128 + kk / 2 + sg * 16;
#pragma unroll
        for (int j = 0; j < 4; j++) {
            cpasync16(wsb + (unsigned)(s * 128 * GQ + row * GQ + sg * 16 + 4 * j) * 4u, ws + 4 * j);
            cpasync16(xsb + (unsigned)(s * 128 * GQ + row * GQ + sg * 16 + 4 * j) * 4u, xs + 4 * j);
        }
        asm volatile("cp.async.commit_group;");
    };

    fill(0, 0);
    for (int ch = 0; ch < 4; ++ch) {
        if (ch < 3) {
            fill((ch + 1) * 64, (ch + 1) & 1);
            asm volatile("cp.async.wait_group 1;");
        } else {
            asm volatile("cp.async.wait_group 0;");
        }
        __syncthreads();
        unsigned wbase = wsb + (unsigned)((ch & 1) * 128 * GQ) * 4u;
        unsigned xbase = xsb + (unsigned)((ch & 1) * 128 * GQ) * 4u;
#pragma unroll
        for (int ks = 0; ks < 4; ks++) {
            unsigned bb[8][2];
#pragma unroll
            for (int np = 0; np < 4; np++) {
                unsigned r[4];
                ldm4(r, xbase + ((unsigned)((64 * nh + 16 * np) * GQ + 8 * ks) + bRow) * 4u);
                bb[2*np][0] = r[0]; bb[2*np][1] = r[1];
                bb[2*np+1][0] = r[2]; bb[2*np+1][1] = r[3];
            }
#pragma unroll
            for (int mt = 0; mt < 2; mt++) {
                unsigned a[4];
                ldm4(a, wbase + ((unsigned)((32 * head + 16 * mt) * GQ + 8 * ks) + aRow) * 4u);
#pragma unroll
                for (int nt = 0; nt < 8; nt++)
                    mma_f16(acc[mt][nt], a[0], a[1], a[2], a[3], bb[nt][0], bb[nt][1]);
            }
        }
        __syncthreads();
    }

    if (sel < 2) {
        unsigned* dst = sel ? kh : qh;
        const float scale = (sel == 0) ? 14.426950408889634f : 1.f;
#pragma unroll
        for (int nt = 0; nt < 8; nt++) {
#pragma unroll
            for (int par = 0; par < 2; par++) {
                float ss = acc[0][nt][par] * acc[0][nt][par]
                         + acc[0][nt][par + 2] * acc[0][nt][par + 2]
                         + acc[1][nt][par] * acc[1][nt][par]
                         + acc[1][nt][par + 2] * acc[1][nt][par + 2];
                ss += __shfl_xor_sync(0xffffffffu, ss, 4);
                ss += __shfl_xor_sync(0xffffffffu, ss, 8);
                ss += __shfl_xor_sync(0xffffffffu, ss, 16);
                float inv = scale / fmaxf(sqrtf(ss), 1e-12f);
                size_t base = ((size_t)(b * 4 + head) * NPIX + pix0 + 8 * nt + 2 * c + par) * 16;
#pragma unroll
                for (int mt = 0; mt < 2; mt++) {
                    float v0 = acc[mt][nt][par] * inv;
                    float v1 = acc[mt][nt][par + 2] * inv;
                    float w0 = __shfl_xor_sync(0xffffffffu, v0, 4);
                    float w1 = __shfl_xor_sync(0xffffffffu, v1, 4);
                    if (!(g & 1)) {
                        dst[base + 8 * mt + (g >> 1)]     = packh2(w0, v0);
                        dst[base + 8 * mt + 4 + (g >> 1)] = packh2(w1, v1);
                    }
                }
            }
        }
    } else {
#pragma unroll
        for (int mt = 0; mt < 2; mt++)
#pragma unroll
            for (int dh = 0; dh < 2; dh++) {
                int d = 16 * mt + 8 * dh + g;
#pragma unroll
                for (int nt = 0; nt < 8; nt++) {
                    unsigned pv = packh2(acc[mt][nt][2 * dh + 1], acc[mt][nt][2 * dh]);
                    vh[((size_t)(b * 4 + head) * 32 + d) * (NPIX / 2) + (pix0 + 8 * nt) / 2 + c] = pv;
                }
            }
    }
}

// ---------------------------------------------------------------------------
// Split-fp16 output projection (unchanged).
// ---------------------------------------------------------------------------
#define GO 12
__global__ __launch_bounds__(128) void gemm_out_h(
    const unsigned* __restrict__ whi, const unsigned* __restrict__ wlo,
    const unsigned* __restrict__ xhi, const unsigned* __restrict__ xlo,
    float* __restrict__ out, const float* __restrict__ bias)
{
    __shared__ unsigned sWh[2][128 * GO], sWl[2][128 * GO];
    __shared__ unsigned sXh[2][64 * GO],  sXl[2][64 * GO];

    const int b = blockIdx.z;
    const int row0 = blockIdx.y * 128, pix0 = blockIdx.x * 64;
    const int tid = threadIdx.x, lane = tid & 31, warp = tid >> 5;
    const int g = lane >> 2, c = lane & 3;
    const unsigned whb = (unsigned)__cvta_generic_to_shared(&sWh[0][0]);
    const unsigned wlb = (unsigned)__cvta_generic_to_shared(&sWl[0][0]);
    const unsigned xhb = (unsigned)__cvta_generic_to_shared(&sXh[0][0]);
    const unsigned xlb = (unsigned)__cvta_generic_to_shared(&sXl[0][0]);
    const unsigned* xhs = xhi + (size_t)b * NPIX * 64;
    const unsigned* xls = xlo + (size_t)b * NPIX * 64;
    float* outb = out + (size_t)b * 256 * NPIX;

    float acc[2][8][4];
#pragma unroll
    for (int mt = 0; mt < 2; mt++)
#pragma unroll
        for (int nt = 0; nt < 8; nt++)
#pragma unroll
            for (int r = 0; r < 4; r++) acc[mt][nt][r] = 0.f;

    auto fill = [&](int kk, int s) {
        const unsigned* wh_ = whi + (size_t)(row0 + tid) * 64 + kk / 2;
        const unsigned* wl_ = wlo + (size_t)(row0 + tid) * 64 + kk / 2;
        cpasync16(whb + (unsigned)(s * 128 * GO + tid * GO) * 4u, wh_);
        cpasync16(whb + (unsigned)(s * 128 * GO + tid * GO + 4) * 4u, wh_ + 4);
        cpasync16(wlb + (unsigned)(s * 128 * GO + tid * GO) * 4u, wl_);
        cpasync16(wlb + (unsigned)(s * 128 * GO + tid * GO + 4) * 4u, wl_ + 4);
        int row = tid >> 1, sg = tid & 1;
        cpasync16(xhb + (unsigned)(s * 64 * GO + row * GO + sg * 4) * 4u,
                  xhs + (size_t)(pix0 + row) * 64 + kk / 2 + sg * 4);
        cpasync16(xlb + (unsigned)(s * 64 * GO + row * GO + sg * 4) * 4u,
                  xls + (size_t)(pix0 + row) * 64 + kk / 2 + sg * 4);
        asm volatile("cp.async.commit_group;");
    };

    fill(0, 0);
    for (int ch = 0; ch < 8; ++ch) {
        if (ch < 7) {
            fill((ch + 1) * 16, (ch + 1) & 1);
            asm volatile("cp.async.wait_group 1;");
        } else {
            asm volatile("cp.async.wait_group 0;");
        }
        __syncthreads();
        const int s = ch & 1;
        const unsigned* wh0 = &sWh[s][0];
        const unsigned* wl0 = &sWl[s][0];
        const unsigned* xh0 = &sXh[s][0];
        const unsigned* xl0 = &sXl[s][0];
        unsigned bh[8][2], bl[8][2];
#pragma unroll
        for (int nt = 0; nt < 8; nt++) {
            bh[nt][0] = xh0[(8 * nt + g) * GO + c];
            bh[nt][1] = xh0[(8 * nt + g) * GO + c + 4];
            bl[nt][0] = xl0[(8 * nt + g) * GO + c];
            bl[nt][1] = xl0[(8 * nt + g) * GO + c + 4];
        }
#pragma unroll
        for (int mt = 0; mt < 2; mt++) {
            int mrow = 32 * warp + 16 * mt;
            unsigned ah0 = wh0[(mrow + g) * GO + c],     ah1 = wh0[(mrow + 8 + g) * GO + c];
            unsigned ah2 = wh0[(mrow + g) * GO + c + 4], ah3 = wh0[(mrow + 8 + g) * GO + c + 4];
            unsigned al0 = wl0[(mrow + g) * GO + c],     al1 = wl0[(mrow + 8 + g) * GO + c];
            unsigned al2 = wl0[(mrow + g) * GO + c + 4], al3 = wl0[(mrow + 8 + g) * GO + c + 4];
#pragma unroll
            for (int nt = 0; nt < 8; nt++) {
                mma_f16(acc[mt][nt], ah0, ah1, ah2, ah3, bh[nt][0], bh[nt][1]);
                mma_f16(acc[mt][nt], ah0, ah1, ah2, ah3, bl[nt][0], bl[nt][1]);
                mma_f16(acc[mt][nt], al0, al1, al2, al3, bh[nt][0], bh[nt][1]);
            }
        }
        __syncthreads();
    }

#pragma unroll
    for (int mt = 0; mt < 2; mt++) {
        int r0 = row0 + 32 * warp + 16 * mt + g;
        float b0 = bias[r0], b1 = bias[r0 + 8];
#pragma unroll
        for (int nt = 0; nt < 8; nt++) {
            int col = pix0 + 8 * nt + 2 * c;
            *(float2*)&outb[(size_t)r0 * NPIX + col] =
                make_float2(acc[mt][nt][0] + b0, acc[mt][nt][1] + b0);
            *(float2*)&outb[(size_t)(r0 + 8) * NPIX + col] =
                make_float2(acc[mt][nt][2] + b1, acc[mt][nt][3] + b1);
        }
    }
}

// ---------------------------------------------------------------------------
// fp16 flash, q-major S; l via hadd2 + fp32 adds on the idle ALU/FMA pipes
// (the two Oex ones-MMAs per kc are GONE from the binding tensor pipe).
// ---------------------------------------------------------------------------
#define SKH 20
#define SVH 68
#define FSTAGE (128 * SKH + 32 * SVH)

__global__ __launch_bounds__(128, 4) void flash_h_kernel(
    const unsigned* __restrict__ qh, const unsigned* __restrict__ kh,
    const unsigned* __restrict__ vh, unsigned* __restrict__ aohi,
    unsigned* __restrict__ aolo)
{
    __shared__ unsigned sm[2 * FSTAGE];

    const int tid = threadIdx.x, lane = tid & 31, warp = tid >> 5;
    const int g = lane >> 2, c = lane & 3;
    const int bh = blockIdx.y, b = bh >> 2, h = bh & 3;
    const int qw = blockIdx.x * 128 + warp * 32;

    const unsigned* qbh = qh + (size_t)bh * NPIX * 16;
    const unsigned* kbh = kh + (size_t)bh * NPIX * 16;
    const unsigned* vbh = vh + (size_t)bh * 32 * (NPIX / 2);
    const unsigned sbase = (unsigned)__cvta_generic_to_shared(sm);
    const unsigned kOff = (unsigned)(((lane & 7) + 8 * ((lane >> 4) & 1)) * SKH + 4 * ((lane >> 3) & 1));
    const unsigned vOff = (unsigned)(((lane & 7) + 8 * ((lane >> 4) & 1)) * SVH + 4 * ((lane >> 3) & 1));

    unsigned aq[2][2][4];
#pragma unroll
    for (int mq = 0; mq < 2; mq++) {
        const unsigned* q0 = qbh + (size_t)(qw + 16 * mq + g) * 16;
        const unsigned* q1 = qbh + (size_t)(qw + 16 * mq + 8 + g) * 16;
#pragma unroll
        for (int ks = 0; ks < 2; ks++) {
            aq[mq][ks][0] = q0[8 * ks + c];
            aq[mq][ks][1] = q1[8 * ks + c];
            aq[mq][ks][2] = q0[8 * ks + c + 4];
            aq[mq][ks][3] = q1[8 * ks + c + 4];
        }
    }

    float O[2][4][4];
    float lq[2], lq8[2];
#pragma unroll
    for (int mq = 0; mq < 2; mq++) {
#pragma unroll
        for (int nd = 0; nd < 4; nd++)
#pragma unroll
            for (int r = 0; r < 4; r++) O[mq][nd][r] = 0.f;
        lq[mq] = 0.f; lq8[mq] = 0.f;
    }

    auto fill = [&](int it, int s) {
        unsigned base = sbase + (unsigned)(s * FSTAGE) * 4u;
        int j0 = it * 128;
#pragma unroll
        for (int r = 0; r < 4; r++) {
            int id = tid + r * 128;
            int row = id >> 2, j = id & 3;
            cpasync16(base + (unsigned)(row * SKH + 4 * j) * 4u,
                      kbh + (size_t)(j0 + row) * 16 + 4 * j);
            int d = id >> 4, jj = id & 15;
            cpasync16(base + (unsigned)(128 * SKH + d * SVH + 4 * jj) * 4u,
                      vbh + (size_t)d * (NPIX / 2) + j0 / 2 + 4 * jj);
        }
        asm volatile("cp.async.commit_group;");
    };

    fill(0, 0);

    for (int it = 0; it < 32; ++it) {
        asm volatile("cp.async.wait_group 0;");
        __syncthreads();
        if (it < 31) fill(it + 1, (it + 1) & 1);

        const unsigned kb = sbase + (unsigned)((it & 1) * FSTAGE) * 4u;
        const unsigned vb = kb + (unsigned)(128 * SKH) * 4u;

#pragma unroll
        for (int kc = 0; kc < 8; kc++) {
            unsigned kf0[4], kf1[4];
            ldm4(kf0, kb + ((unsigned)(16 * kc * SKH) + kOff) * 4u);
            ldm4(kf1, kb + ((unsigned)(16 * kc * SKH + 8) + kOff) * 4u);

            float acc[2][2][4];
#pragma unroll
            for (int mq = 0; mq < 2; mq++)
#pragma unroll
                for (int nt = 0; nt < 2; nt++) {
#pragma unroll
                    for (int r = 0; r < 4; r++) acc[mq][nt][r] = 0.f;
                    mma_f16(acc[mq][nt], aq[mq][0][0], aq[mq][0][1], aq[mq][0][2], aq[mq][0][3],
                            kf0[2 * nt], kf0[2 * nt + 1]);
                    mma_f16(acc[mq][nt], aq[mq][1][0], aq[mq][1][1], aq[mq][1][2], aq[mq][1][3],
                            kf1[2 * nt], kf1[2 * nt + 1]);
                }

            unsigned vf0[4], vf1[4];
            ldm4(vf0, vb + ((unsigned)(8 * kc) + vOff) * 4u);
            ldm4(vf1, vb + ((unsigned)(16 * SVH + 8 * kc) + vOff) * 4u);

            unsigned pa[2][4];
#pragma unroll
            for (int mq = 0; mq < 2; mq++) {
                pa[mq][0] = h2exp2(packh2(acc[mq][0][1], acc[mq][0][0]));  // row g,   keys 2c
                pa[mq][1] = h2exp2(packh2(acc[mq][0][3], acc[mq][0][2]));  // row g+8, keys 2c
                pa[mq][2] = h2exp2(packh2(acc[mq][1][1], acc[mq][1][0]));  // row g,   keys 8+2c
                pa[mq][3] = h2exp2(packh2(acc[mq][1][3], acc[mq][1][2]));  // row g+8, keys 8+2c
                // l partial sums on FMA/ALU pipes (tensor pipe freed)
                __half2 sg  = __hadd2(*(__half2*)&pa[mq][0], *(__half2*)&pa[mq][2]);
                __half2 sg8 = __hadd2(*(__half2*)&pa[mq][1], *(__half2*)&pa[mq][3]);
                float2 f  = __half22float2(sg);
                float2 f8 = __half22float2(sg8);
                lq[mq]  += f.x + f.y;
                lq8[mq] += f8.x + f8.y;
            }

#pragma unroll
            for (int mq = 0; mq < 2; mq++) {
                mma_f16(O[mq][0], pa[mq][0], pa[mq][1], pa[mq][2], pa[mq][3], vf0[0], vf0[1]);
                mma_f16(O[mq][1], pa[mq][0], pa[mq][1], pa[mq][2], pa[mq][3], vf0[2], vf0[3]);
                mma_f16(O[mq][2], pa[mq][0], pa[mq][1], pa[mq][2], pa[mq][3], vf1[0], vf1[1]);
                mma_f16(O[mq][3], pa[mq][0], pa[mq][1], pa[mq][2], pa[mq][3], vf1[2], vf1[3]);
            }
        }
    }

    // finish l: sum over the 4-lane c-group (this thread holds 4 of 16 keys/row)
    float linvq[2], linvq8[2];
#pragma unroll
    for (int mq = 0; mq < 2; mq++) {
        float a = lq[mq];
        a += __shfl_xor_sync(0xffffffffu, a, 1);
        a += __shfl_xor_sync(0xffffffffu, a, 2);
        linvq[mq] = 1.f / a;
        float a8 = lq8[mq];
        a8 += __shfl_xor_sync(0xffffffffu, a8, 1);
        a8 += __shfl_xor_sync(0xffffffffu, a8, 2);
        linvq8[mq] = 1.f / a8;
    }

    unsigned* aoh = aohi + (size_t)b * NPIX * 64;
    unsigned* aol = aolo + (size_t)b * NPIX * 64;
#pragma unroll
    for (int mq = 0; mq < 2; mq++)
#pragma unroll
        for (int nd = 0; nd < 4; nd++) {
            int q0 = qw + 16 * mq + g;
            int pr = h * 16 + 4 * nd + c;
            float o0 = O[mq][nd][0] * linvq[mq];
            float o1 = O[mq][nd][1] * linvq[mq];
            __half h0 = __float2half_rn(o0), h1 = __float2half_rn(o1);
            aoh[(size_t)q0 * 64 + pr] =
                (unsigned)__half_as_ushort(h0) | ((unsigned)__half_as_ushort(h1) << 16);
            aol[(size_t)q0 * 64 + pr] =
                packh2(o1 - __half2float(h1), o0 - __half2float(h0));
            float o2 = O[mq][nd][2] * linvq8[mq];
            float o3 = O[mq][nd][3] * linvq8[mq];
            __half h2 = __float2half_rn(o2), h3 = __float2half_rn(o3);
            aoh[(size_t)(q0 + 8) * 64 + pr] =
                (unsigned)__half_as_ushort(h2) | ((unsigned)__half_as_ushort(h3) << 16);
            aol[(size_t)(q0 + 8) * 64 + pr] =
                packh2(o3 - __half2float(h3), o2 - __half2float(h2));
        }
}

// ---------------------------------------------------------------------------
extern "C" void kernel_launch(void* const* d_in, const int* in_sizes, int n_in,
                              void* d_out, int out_size)
{
    const float* x     = (const float*)d_in[0];
    const float* w_qkv = (const float*)d_in[1];
    const float* w_out = (const float*)d_in[2];
    const float* b_out = (const float*)d_in[3];
    float* out = (float*)d_out;

    static unsigned *qh = nullptr, *kh = nullptr, *vh = nullptr, *wh = nullptr, *xh = nullptr;
    static unsigned *w2hi = nullptr, *w2lo = nullptr, *aohi = nullptr, *aolo = nullptr;
    if (!qh) {
        cudaGetSymbolAddress((void**)&qh,   g_qh);
        cudaGetSymbolAddress((void**)&kh,   g_kh);
        cudaGetSymbolAddress((void**)&vh,   g_vh);
        cudaGetSymbolAddress((void**)&wh,   g_wh);
        cudaGetSymbolAddress((void**)&xh,   g_xh);
        cudaGetSymbolAddress((void**)&w2hi, g_w2hi);
        cudaGetSymbolAddress((void**)&w2lo, g_w2lo);
        cudaGetSymbolAddress((void**)&aohi, g_aohi);
        cudaGetSymbolAddress((void**)&aolo, g_aolo);
        cudaFuncSetAttribute(gemm_qkv_h, cudaFuncAttributeMaxDynamicSharedMemorySize, QKVSM);
    }

    cvtw_kernel<<<192, 256>>>(w_qkv, wh, w_out, w2hi, w2lo);
    xcvt_kernel<<<dim3(NPIX / 64, 256 / 64, NB), 256>>>(x, xh);

    dim3 g1(NPIX / 128, 3, NB);
    gemm_qkv_h<<<g1, 256, QKVSM>>>(wh, xh, qh, kh, vh);

    dim3 g3(NPIX / 128, 16);
    flash_h_kernel<<<g3, 128>>>(qh, kh, vh, aohi, aolo);

    dim3 g4(NPIX / 64, 2, NB);
    gemm_out_h<<<g4, 128>>>(w2hi, w2lo, aohi, aolo, out, b_out);
}